// round 7
// baseline (speedup 1.0000x reference)
#include <cuda_runtime.h>
#include <cuda_bf16.h>

#define N_NODES 10000
#define N_EDGES 640000
#define F_IN 128
#define F_H 128
#define F_OUT 64

// ---------------- scratch (device globals; no allocation allowed) ----------------
__device__ int   g_is_i32;               // 1 => indices are int32, 0 => int64
__device__ int   g_deg_in [N_NODES];
__device__ int   g_deg_out[N_NODES];
__device__ float g_rs_in  [N_NODES];
__device__ float g_rs_out [N_NODES];
__device__ int   g_row_ptr[N_NODES + 1];
__device__ int   g_cursor [N_NODES];
__device__ int   g_src_sorted[N_EDGES];
__device__ __align__(16) float g_A1[N_NODES * F_H];    // X @ W1 (unscaled)
__device__ __align__(16) float g_H [N_NODES * F_H];    // layer-1 output (post relu)
__device__ __align__(16) float g_A2[N_NODES * F_OUT];  // (H @ W2) * rs_out

// ---------------- init: zero degrees; block 0 also detects index dtype ----------
__global__ void k_init(const int* __restrict__ src) {
    int i = blockIdx.x * blockDim.x + threadIdx.x;
    if (i < N_NODES) { g_deg_in[i] = 0; g_deg_out[i] = 0; }
    if (blockIdx.x == 0) {
        int v = 0;
        #pragma unroll
        for (int r = 0; r < 8; r++) v |= src[2 * (threadIdx.x + 256 * r) + 1];
        #pragma unroll
        for (int o = 16; o; o >>= 1) v |= __shfl_xor_sync(0xFFFFFFFFu, v, o);
        __shared__ int sred[8];
        if ((threadIdx.x & 31) == 0) sred[threadIdx.x >> 5] = v;
        __syncthreads();
        if (threadIdx.x == 0) {
            int a = 0;
            #pragma unroll
            for (int w = 0; w < 8; w++) a |= sred[w];
            g_is_i32 = (a != 0) ? 1 : 0;
        }
    }
}

// 4 edges per thread (independent atomic chains -> MLP=4)
__global__ void k_degrees(const int* __restrict__ src,
                          const int* __restrict__ dst) {
    const int i32 = g_is_i32;
    int base = blockIdx.x * 1024 + threadIdx.x;
    int s[4], d[4];
    #pragma unroll
    for (int k = 0; k < 4; k++) {
        int e = base + k * 256;
        s[k] = i32 ? src[e] : src[2 * e];
        d[k] = i32 ? dst[e] : dst[2 * e];
    }
    #pragma unroll
    for (int k = 0; k < 4; k++) {
        atomicAdd(&g_deg_out[s[k]], 1);
        atomicAdd(&g_deg_in [d[k]], 1);
    }
}

// ---------------- fused: rsqrt of degrees + single-pass exclusive scan ---------
__global__ void k_scan_rsqrt() {
    constexpr int PT = 10;   // 1024*10 >= 10000
    const int tid  = threadIdx.x;
    const int lane = tid & 31, warp = tid >> 5;

    for (int i = tid; i < N_NODES; i += 1024) {
        g_rs_in [i] = rsqrtf((float)max(g_deg_in [i], 1));
        g_rs_out[i] = rsqrtf((float)max(g_deg_out[i], 1));
    }

    int base = tid * PT;
    int v[PT];
    int tot = 0;
    #pragma unroll
    for (int j = 0; j < PT; j++) {
        int i = base + j;
        v[j] = (i < N_NODES) ? g_deg_in[i] : 0;
        tot += v[j];
    }

    __shared__ int wsum[32];
    int x = tot;
    #pragma unroll
    for (int o = 1; o < 32; o <<= 1) {
        int t = __shfl_up_sync(0xFFFFFFFFu, x, o);
        if (lane >= o) x += t;
    }
    if (lane == 31) wsum[warp] = x;
    __syncthreads();
    if (warp == 0) {
        int w = wsum[lane];
        #pragma unroll
        for (int o = 1; o < 32; o <<= 1) {
            int t = __shfl_up_sync(0xFFFFFFFFu, w, o);
            if (lane >= o) w += t;
        }
        wsum[lane] = w;
    }
    __syncthreads();
    int excl = (x - tot) + (warp ? wsum[warp - 1] : 0);

    if (tid == 0) g_row_ptr[0] = 0;
    int run = excl;
    #pragma unroll
    for (int j = 0; j < PT; j++) {
        int i = base + j;
        int prev = run;
        run += v[j];
        if (i < N_NODES) {
            g_row_ptr[i + 1] = run;
            g_cursor[i]      = prev;
        }
    }
}

// 4 edges per thread
__global__ void k_fill(const int* __restrict__ src,
                       const int* __restrict__ dst) {
    const int i32 = g_is_i32;
    int base = blockIdx.x * 1024 + threadIdx.x;
    int s[4], d[4], p[4];
    #pragma unroll
    for (int k = 0; k < 4; k++) {
        int e = base + k * 256;
        s[k] = i32 ? src[e] : src[2 * e];
        d[k] = i32 ? dst[e] : dst[2 * e];
    }
    #pragma unroll
    for (int k = 0; k < 4; k++) p[k] = atomicAdd(&g_cursor[d[k]], 1);
    #pragma unroll
    for (int k = 0; k < 4; k++) g_src_sorted[p[k]] = s[k];
}

// ---------------- GEMM body (256 thr, BM=BN=64, BK=16, 4x4 microtile) ---------
template <bool SCALE>
__device__ __forceinline__ void gemm_body(
    const float* __restrict__ A, const float* __restrict__ B,
    float* __restrict__ C, int M, int N, int K)
{
    __shared__ __align__(16) float As[16][68];
    __shared__ __align__(16) float Bs[16][64];
    int tid = threadIdx.x;
    int tx = tid & 15, ty = tid >> 4;
    int bm = blockIdx.y * 64;
    int bn = blockIdx.x * 64;
    float acc[4][4] = {};
    for (int k0 = 0; k0 < K; k0 += 16) {
        {
            int r = tid >> 2;
            int c = (tid & 3) * 4;
            float4 v = make_float4(0.f, 0.f, 0.f, 0.f);
            if (bm + r < M)
                v = *reinterpret_cast<const float4*>(&A[(size_t)(bm + r) * K + k0 + c]);
            As[c + 0][r] = v.x; As[c + 1][r] = v.y;
            As[c + 2][r] = v.z; As[c + 3][r] = v.w;
        }
        {
            int r = tid >> 4;
            int c = (tid & 15) * 4;
            float4 v = *reinterpret_cast<const float4*>(&B[(size_t)(k0 + r) * N + bn + c]);
            Bs[r][c + 0] = v.x; Bs[r][c + 1] = v.y;
            Bs[r][c + 2] = v.z; Bs[r][c + 3] = v.w;
        }
        __syncthreads();
        #pragma unroll
        for (int k = 0; k < 16; k++) {
            float4 a = *reinterpret_cast<const float4*>(&As[k][ty * 4]);
            float4 b = *reinterpret_cast<const float4*>(&Bs[k][tx * 4]);
            float av[4] = {a.x, a.y, a.z, a.w};
            float bv[4] = {b.x, b.y, b.z, b.w};
            #pragma unroll
            for (int i = 0; i < 4; i++)
                #pragma unroll
                for (int j = 0; j < 4; j++)
                    acc[i][j] += av[i] * bv[j];
        }
        __syncthreads();
    }
    #pragma unroll
    for (int i = 0; i < 4; i++) {
        int m = bm + ty * 4 + i;
        if (m < M) {
            float s = SCALE ? g_rs_out[m] : 1.0f;
            float4 o = make_float4(acc[i][0] * s, acc[i][1] * s,
                                   acc[i][2] * s, acc[i][3] * s);
            *reinterpret_cast<float4*>(&C[(size_t)m * N + bn + tx * 4]) = o;
        }
    }
}

__global__ void k_gemm1(const float* __restrict__ X, const float* __restrict__ W1) {
    gemm_body<false>(X, W1, &g_A1[0], N_NODES, F_H, F_IN);   // unscaled
}
__global__ void k_gemm2(const float* __restrict__ W2) {
    gemm_body<true>(&g_H[0], W2, &g_A2[0], N_NODES, F_OUT, F_H);
}

// ---------------- SpMM (CSR gather, float4) + fused epilogue ------------------
// EDGE_SCALE: multiply each gathered row by rs_out[src] (staged in smem).
template <int F, bool RELU, bool EDGE_SCALE>
__device__ __forceinline__ void spmm_body(const float* __restrict__ X,
                                          const float* __restrict__ bias,
                                          float* __restrict__ out)
{
    constexpr int C = F / 4;
    constexpr int G = 256 / C;
    const int tid   = threadIdx.x;
    const int chunk = tid & (C - 1);
    const int grp   = tid / C;
    const int row   = blockIdx.x;
    const int beg   = g_row_ptr[row];
    const int end   = g_row_ptr[row + 1];

    __shared__ int sidx[256];
    __shared__ float srs[256];
    __shared__ __align__(16) float4 red[G][C];

    const float4* __restrict__ X4 = reinterpret_cast<const float4*>(X);

    float4 acc = make_float4(0.f, 0.f, 0.f, 0.f);
    for (int base = beg; base < end; base += 256) {
        int cnt = min(256, end - base);
        if (tid < cnt) {
            int s = g_src_sorted[base + tid];
            sidx[tid] = s;
            if (EDGE_SCALE) srs[tid] = g_rs_out[s];
        }
        __syncthreads();
        for (int i = grp; i < cnt; i += G) {
            float4 v = X4[(size_t)sidx[i] * C + chunk];
            if (EDGE_SCALE) {
                float sc = srs[i];
                acc.x += v.x * sc; acc.y += v.y * sc;
                acc.z += v.z * sc; acc.w += v.w * sc;
            } else {
                acc.x += v.x; acc.y += v.y; acc.z += v.z; acc.w += v.w;
            }
        }
        __syncthreads();
    }
    red[grp][chunk] = acc;
    __syncthreads();
    if (tid < C) {
        float4 s = red[0][tid];
        #pragma unroll
        for (int g = 1; g < G; g++) {
            float4 v = red[g][tid];
            s.x += v.x; s.y += v.y; s.z += v.z; s.w += v.w;
        }
        float r = g_rs_in[row];
        float4 b = reinterpret_cast<const float4*>(bias)[tid];
        s.x = s.x * r + b.x; s.y = s.y * r + b.y;
        s.z = s.z * r + b.z; s.w = s.w * r + b.w;
        if (RELU) {
            s.x = fmaxf(s.x, 0.f); s.y = fmaxf(s.y, 0.f);
            s.z = fmaxf(s.z, 0.f); s.w = fmaxf(s.w, 0.f);
        }
        reinterpret_cast<float4*>(out)[(size_t)row * C + tid] = s;
    }
}

__global__ void k_spmm1(const float* __restrict__ b1) {
    spmm_body<F_H, true, true>(&g_A1[0], b1, &g_H[0]);      // edge-scaled
}
__global__ void k_spmm2(const float* __restrict__ b2, float* __restrict__ out) {
    spmm_body<F_OUT, false, false>(&g_A2[0], b2, out);
}

// ---------------- launch ----------------
extern "C" void kernel_launch(void* const* d_in, const int* in_sizes, int n_in,
                              void* d_out, int out_size) {
    const float* X   = (const float*)d_in[0];
    const int*   src = (const int*)d_in[1];   // int32 or int64 (device-detected)
    const int*   dst = (const int*)d_in[2];
    const float* W1  = (const float*)d_in[3];
    const float* b1  = (const float*)d_in[4];
    const float* W2  = (const float*)d_in[5];
    const float* b2  = (const float*)d_in[6];
    float* out = (float*)d_out;

    // side stream + events, created once on the (non-captured) correctness call
    static cudaStream_t s2 = nullptr;
    static cudaEvent_t  ev_fork = nullptr, ev_join = nullptr;
    if (s2 == nullptr) {
        cudaStreamCreateWithFlags(&s2, cudaStreamNonBlocking);
        cudaEventCreateWithFlags(&ev_fork, cudaEventDisableTiming);
        cudaEventCreateWithFlags(&ev_join, cudaEventDisableTiming);
    }

    const int NB_NODE = (N_NODES + 255) / 256;
    const int NB_EDGE4 = N_EDGES / 1024;      // 625 (4 edges/thread)

    // fork: gemm1 depends only on inputs -> run on s2 in parallel with CSR build
    cudaEventRecord(ev_fork, 0);
    cudaStreamWaitEvent(s2, ev_fork, 0);
    dim3 grid1(F_H / 64, (N_NODES + 63) / 64);
    k_gemm1<<<grid1, 256, 0, s2>>>(X, W1);
    cudaEventRecord(ev_join, s2);

    // main stream: CSR build
    k_init      <<<NB_NODE, 256>>>(src);
    k_degrees   <<<NB_EDGE4, 256>>>(src, dst);
    k_scan_rsqrt<<<1, 1024>>>();
    k_fill      <<<NB_EDGE4, 256>>>(src, dst);

    // join, then layer-1 aggregation and layer 2
    cudaStreamWaitEvent(0, ev_join, 0);
    k_spmm1<<<N_NODES, 256>>>(b1);

    dim3 grid2(F_OUT / 64, (N_NODES + 63) / 64);
    k_gemm2<<<grid2, 256>>>(W2);
    k_spmm2<<<N_NODES, 256>>>(b2, out);
}

// round 8
// speedup vs baseline: 1.3851x; 1.3851x over previous
#include <cuda_runtime.h>
#include <cuda_bf16.h>

#define N_NODES 10000
#define N_EDGES 640000
#define F_IN 128
#define F_H 128
#define F_OUT 64

// ---------------- scratch (device globals; no allocation allowed) ----------------
__device__ int   g_is_i32;               // 1 => indices are int32, 0 => int64
__device__ int   g_deg_in [N_NODES];
__device__ int   g_deg_out[N_NODES];
__device__ float g_rs_in  [N_NODES];
__device__ float g_rs_out [N_NODES];
__device__ int   g_row_ptr[N_NODES + 1];
__device__ int   g_cursor [N_NODES];
__device__ int   g_src_sorted[N_EDGES];
__device__ __align__(16) float g_A1[N_NODES * F_H];    // (X @ W1) * rs_out
__device__ __align__(16) float g_H [N_NODES * F_H];    // layer-1 output (post relu)
__device__ __align__(16) float g_A2[N_NODES * F_OUT];  // (H @ W2) * rs_out

// ---------------- init: zero degrees; block 0 also detects index dtype ----------
__global__ void k_init(const int* __restrict__ src) {
    int i = blockIdx.x * blockDim.x + threadIdx.x;
    if (i < N_NODES) { g_deg_in[i] = 0; g_deg_out[i] = 0; }
    if (blockIdx.x == 0) {
        int v = 0;
        #pragma unroll
        for (int r = 0; r < 8; r++) v |= src[2 * (threadIdx.x + 256 * r) + 1];
        #pragma unroll
        for (int o = 16; o; o >>= 1) v |= __shfl_xor_sync(0xFFFFFFFFu, v, o);
        __shared__ int sred[8];
        if ((threadIdx.x & 31) == 0) sred[threadIdx.x >> 5] = v;
        __syncthreads();
        if (threadIdx.x == 0) {
            int a = 0;
            #pragma unroll
            for (int w = 0; w < 8; w++) a |= sred[w];
            g_is_i32 = (a != 0) ? 1 : 0;
        }
    }
}

// 4 edges per thread (independent atomic chains -> MLP=4)
__global__ void k_degrees(const int* __restrict__ src,
                          const int* __restrict__ dst) {
    const int i32 = g_is_i32;
    int base = blockIdx.x * 1024 + threadIdx.x;
    int s[4], d[4];
    #pragma unroll
    for (int k = 0; k < 4; k++) {
        int e = base + k * 256;
        s[k] = i32 ? src[e] : src[2 * e];
        d[k] = i32 ? dst[e] : dst[2 * e];
    }
    #pragma unroll
    for (int k = 0; k < 4; k++) {
        atomicAdd(&g_deg_out[s[k]], 1);
        atomicAdd(&g_deg_in [d[k]], 1);
    }
}

// ---------------- fused: rsqrt of degrees + single-pass exclusive scan ---------
// One block, 1024 threads; each thread owns PT=10 contiguous elements.
__global__ void k_scan_rsqrt() {
    constexpr int PT = 10;   // 1024*10 >= 10000
    const int tid  = threadIdx.x;
    const int lane = tid & 31, warp = tid >> 5;

    for (int i = tid; i < N_NODES; i += 1024) {
        g_rs_in [i] = rsqrtf((float)max(g_deg_in [i], 1));
        g_rs_out[i] = rsqrtf((float)max(g_deg_out[i], 1));
    }

    int base = tid * PT;
    int v[PT];
    int tot = 0;
    #pragma unroll
    for (int j = 0; j < PT; j++) {
        int i = base + j;
        v[j] = (i < N_NODES) ? g_deg_in[i] : 0;
        tot += v[j];
    }

    __shared__ int wsum[32];
    int x = tot;
    #pragma unroll
    for (int o = 1; o < 32; o <<= 1) {
        int t = __shfl_up_sync(0xFFFFFFFFu, x, o);
        if (lane >= o) x += t;
    }
    if (lane == 31) wsum[warp] = x;
    __syncthreads();
    if (warp == 0) {
        int w = wsum[lane];
        #pragma unroll
        for (int o = 1; o < 32; o <<= 1) {
            int t = __shfl_up_sync(0xFFFFFFFFu, w, o);
            if (lane >= o) w += t;
        }
        wsum[lane] = w;
    }
    __syncthreads();
    int excl = (x - tot) + (warp ? wsum[warp - 1] : 0);

    if (tid == 0) g_row_ptr[0] = 0;
    int run = excl;
    #pragma unroll
    for (int j = 0; j < PT; j++) {
        int i = base + j;
        int prev = run;
        run += v[j];
        if (i < N_NODES) {
            g_row_ptr[i + 1] = run;
            g_cursor[i]      = prev;
        }
    }
}

// 4 edges per thread
__global__ void k_fill(const int* __restrict__ src,
                       const int* __restrict__ dst) {
    const int i32 = g_is_i32;
    int base = blockIdx.x * 1024 + threadIdx.x;
    int s[4], d[4], p[4];
    #pragma unroll
    for (int k = 0; k < 4; k++) {
        int e = base + k * 256;
        s[k] = i32 ? src[e] : src[2 * e];
        d[k] = i32 ? dst[e] : dst[2 * e];
    }
    #pragma unroll
    for (int k = 0; k < 4; k++) p[k] = atomicAdd(&g_cursor[d[k]], 1);
    #pragma unroll
    for (int k = 0; k < 4; k++) g_src_sorted[p[k]] = s[k];
}

// ---------------- GEMM body (256 thr, BM=BN=64, BK=16, 4x4 microtile) ---------
__device__ __forceinline__ void gemm_rs_body(
    const float* __restrict__ A, const float* __restrict__ B,
    float* __restrict__ C, int M, int N, int K)
{
    __shared__ __align__(16) float As[16][68];
    __shared__ __align__(16) float Bs[16][64];
    int tid = threadIdx.x;
    int tx = tid & 15, ty = tid >> 4;
    int bm = blockIdx.y * 64;
    int bn = blockIdx.x * 64;
    float acc[4][4] = {};
    for (int k0 = 0; k0 < K; k0 += 16) {
        {
            int r = tid >> 2;
            int c = (tid & 3) * 4;
            float4 v = make_float4(0.f, 0.f, 0.f, 0.f);
            if (bm + r < M)
                v = *reinterpret_cast<const float4*>(&A[(size_t)(bm + r) * K + k0 + c]);
            As[c + 0][r] = v.x; As[c + 1][r] = v.y;
            As[c + 2][r] = v.z; As[c + 3][r] = v.w;
        }
        {
            int r = tid >> 4;
            int c = (tid & 15) * 4;
            float4 v = *reinterpret_cast<const float4*>(&B[(size_t)(k0 + r) * N + bn + c]);
            Bs[r][c + 0] = v.x; Bs[r][c + 1] = v.y;
            Bs[r][c + 2] = v.z; Bs[r][c + 3] = v.w;
        }
        __syncthreads();
        #pragma unroll
        for (int k = 0; k < 16; k++) {
            float4 a = *reinterpret_cast<const float4*>(&As[k][ty * 4]);
            float4 b = *reinterpret_cast<const float4*>(&Bs[k][tx * 4]);
            float av[4] = {a.x, a.y, a.z, a.w};
            float bv[4] = {b.x, b.y, b.z, b.w};
            #pragma unroll
            for (int i = 0; i < 4; i++)
                #pragma unroll
                for (int j = 0; j < 4; j++)
                    acc[i][j] += av[i] * bv[j];
        }
        __syncthreads();
    }
    #pragma unroll
    for (int i = 0; i < 4; i++) {
        int m = bm + ty * 4 + i;
        if (m < M) {
            float s = g_rs_out[m];
            float4 o = make_float4(acc[i][0] * s, acc[i][1] * s,
                                   acc[i][2] * s, acc[i][3] * s);
            *reinterpret_cast<float4*>(&C[(size_t)m * N + bn + tx * 4]) = o;
        }
    }
}

__global__ void k_gemm1(const float* __restrict__ X, const float* __restrict__ W1) {
    gemm_rs_body(X, W1, &g_A1[0], N_NODES, F_H, F_IN);
}
__global__ void k_gemm2(const float* __restrict__ W2) {
    gemm_rs_body(&g_H[0], W2, &g_A2[0], N_NODES, F_OUT, F_H);
}

// ---------------- SpMM (CSR gather, scalar per-feature: R4-proven) ------------
template <int F, bool RELU>
__device__ __forceinline__ void spmm_body(const float* __restrict__ X,
                                          const float* __restrict__ bias,
                                          float* __restrict__ out)
{
    const int row = blockIdx.x;
    const int f   = threadIdx.x;
    const int beg = g_row_ptr[row];
    const int end = g_row_ptr[row + 1];
    __shared__ int sidx[256];
    float a0 = 0.f, a1 = 0.f, a2 = 0.f, a3 = 0.f;
    for (int base = beg; base < end; base += 256) {
        int cnt = min(256, end - base);
        for (int i = f; i < cnt; i += F) sidx[i] = g_src_sorted[base + i];
        __syncthreads();
        int i = 0;
        for (; i + 4 <= cnt; i += 4) {
            a0 += X[(size_t)sidx[i + 0] * F + f];
            a1 += X[(size_t)sidx[i + 1] * F + f];
            a2 += X[(size_t)sidx[i + 2] * F + f];
            a3 += X[(size_t)sidx[i + 3] * F + f];
        }
        for (; i < cnt; i++) a0 += X[(size_t)sidx[i] * F + f];
        __syncthreads();
    }
    float v = (a0 + a1 + a2 + a3) * g_rs_in[row] + bias[f];
    if (RELU) v = fmaxf(v, 0.f);
    out[(size_t)row * F + f] = v;
}

__global__ void k_spmm1(const float* __restrict__ b1) {
    spmm_body<F_H, true>(&g_A1[0], b1, &g_H[0]);
}
__global__ void k_spmm2(const float* __restrict__ b2, float* __restrict__ out) {
    spmm_body<F_OUT, false>(&g_A2[0], b2, out);
}

// ---------------- launch ----------------
extern "C" void kernel_launch(void* const* d_in, const int* in_sizes, int n_in,
                              void* d_out, int out_size) {
    const float* X   = (const float*)d_in[0];
    const int*   src = (const int*)d_in[1];   // int32 or int64 (device-detected)
    const int*   dst = (const int*)d_in[2];
    const float* W1  = (const float*)d_in[3];
    const float* b1  = (const float*)d_in[4];
    const float* W2  = (const float*)d_in[5];
    const float* b2  = (const float*)d_in[6];
    float* out = (float*)d_out;

    const int NB_NODE  = (N_NODES + 255) / 256;
    const int NB_EDGE4 = N_EDGES / 1024;      // 625 (4 edges/thread)

    k_init      <<<NB_NODE, 256>>>(src);
    k_degrees   <<<NB_EDGE4, 256>>>(src, dst);
    k_scan_rsqrt<<<1, 1024>>>();
    k_fill      <<<NB_EDGE4, 256>>>(src, dst);

    dim3 grid1(F_H / 64, (N_NODES + 63) / 64);
    k_gemm1<<<grid1, 256>>>(X, W1);
    k_spmm1<<<N_NODES, F_H>>>(b1);

    dim3 grid2(F_OUT / 64, (N_NODES + 63) / 64);
    k_gemm2<<<grid2, 256>>>(W2);
    k_spmm2<<<N_NODES, F_OUT>>>(b2, out);
}

// round 9
// speedup vs baseline: 1.5707x; 1.1340x over previous
#include <cuda_runtime.h>
#include <cuda_bf16.h>

#define N_NODES 10000
#define N_EDGES 640000
#define F_IN 128
#define F_H 128
#define F_OUT 64

// ---------------- scratch (device globals; zero-initialized at load) -----------
__device__ int   g_is_i32;               // 1 => indices are int32, 0 => int64
__device__ int   g_deg_in [N_NODES];     // re-zeroed by k_scan_rsqrt each call
__device__ int   g_deg_out[N_NODES];     // re-zeroed by k_scan_rsqrt each call
__device__ float g_rs_in  [N_NODES];
__device__ float g_rs_out [N_NODES];
__device__ int   g_row_ptr[N_NODES + 1];
__device__ int   g_rank   [N_EDGES];     // rank of edge within its dst row
__device__ int   g_src_sorted[N_EDGES];
__device__ __align__(16) float g_A1[N_NODES * F_H];    // (X @ W1) * rs_out
__device__ __align__(16) float g_H [N_NODES * F_H];    // layer-1 output (post relu)
__device__ __align__(16) float g_A2[N_NODES * F_OUT];  // (H @ W2) * rs_out

// ---------------- dtype detect (single block) ----------------------------------
__global__ void k_detect(const int* __restrict__ src) {
    int v = 0;
    #pragma unroll
    for (int r = 0; r < 8; r++) v |= src[2 * (threadIdx.x + 256 * r) + 1];
    #pragma unroll
    for (int o = 16; o; o >>= 1) v |= __shfl_xor_sync(0xFFFFFFFFu, v, o);
    __shared__ int sred[8];
    if ((threadIdx.x & 31) == 0) sred[threadIdx.x >> 5] = v;
    __syncthreads();
    if (threadIdx.x == 0) {
        int a = 0;
        #pragma unroll
        for (int w = 0; w < 8; w++) a |= sred[w];
        g_is_i32 = (a != 0) ? 1 : 0;
    }
}

// ---------------- degrees + rank capture (1 edge/thread) ------------------------
__global__ void k_degrees(const int* __restrict__ src,
                          const int* __restrict__ dst) {
    int e = blockIdx.x * 256 + threadIdx.x;
    if (e < N_EDGES) {
        const int i32 = g_is_i32;
        int s = i32 ? src[e] : src[2 * e];
        int d = i32 ? dst[e] : dst[2 * e];
        atomicAdd(&g_deg_out[s], 1);                 // no return -> REDG
        g_rank[e] = atomicAdd(&g_deg_in[d], 1);      // return = rank in row
    }
}

// ---------------- fused: rsqrt + single-pass exclusive scan + re-zero -----------
__global__ void k_scan_rsqrt() {
    constexpr int PT = 10;   // 1024*10 >= 10000
    const int tid  = threadIdx.x;
    const int lane = tid & 31, warp = tid >> 5;

    for (int i = tid; i < N_NODES; i += 1024) {
        g_rs_in [i] = rsqrtf((float)max(g_deg_in [i], 1));
        g_rs_out[i] = rsqrtf((float)max(g_deg_out[i], 1));
    }

    int base = tid * PT;
    int v[PT];
    int tot = 0;
    #pragma unroll
    for (int j = 0; j < PT; j++) {
        int i = base + j;
        v[j] = (i < N_NODES) ? g_deg_in[i] : 0;
        tot += v[j];
    }

    __shared__ int wsum[32];
    int x = tot;
    #pragma unroll
    for (int o = 1; o < 32; o <<= 1) {
        int t = __shfl_up_sync(0xFFFFFFFFu, x, o);
        if (lane >= o) x += t;
    }
    if (lane == 31) wsum[warp] = x;
    __syncthreads();
    if (warp == 0) {
        int w = wsum[lane];
        #pragma unroll
        for (int o = 1; o < 32; o <<= 1) {
            int t = __shfl_up_sync(0xFFFFFFFFu, w, o);
            if (lane >= o) w += t;
        }
        wsum[lane] = w;
    }
    __syncthreads();
    int excl = (x - tot) + (warp ? wsum[warp - 1] : 0);

    if (tid == 0) g_row_ptr[0] = 0;
    int run = excl;
    #pragma unroll
    for (int j = 0; j < PT; j++) {
        int i = base + j;
        int prev = run;
        run += v[j];
        if (i < N_NODES) g_row_ptr[i + 1] = run;
        (void)prev;
    }

    // all reads of the degree arrays are done -> zero them for the next call
    __syncthreads();
    for (int i = tid; i < N_NODES; i += 1024) {
        g_deg_in[i] = 0; g_deg_out[i] = 0;
    }
}

// ---------------- fill: atomic-free slot computation ---------------------------
__global__ void k_fill(const int* __restrict__ src,
                       const int* __restrict__ dst) {
    int e = blockIdx.x * 256 + threadIdx.x;
    if (e < N_EDGES) {
        const int i32 = g_is_i32;
        int s = i32 ? src[e] : src[2 * e];
        int d = i32 ? dst[e] : dst[2 * e];
        g_src_sorted[g_row_ptr[d] + g_rank[e]] = s;
    }
}

// ---------------- GEMM body (256 thr, BM=BN=64, BK=16, 4x4, FFMA2 inner) ------
__device__ __forceinline__ void gemm_rs_body(
    const float* __restrict__ A, const float* __restrict__ B,
    float* __restrict__ C, int M, int N, int K)
{
    __shared__ __align__(16) float As[16][68];   // row stride 272B = 17*16B
    __shared__ __align__(16) float Bs[16][64];
    int tid = threadIdx.x;
    int tx = tid & 15, ty = tid >> 4;
    int bm = blockIdx.y * 64;
    int bn = blockIdx.x * 64;
    unsigned long long acc2[4][2] = {};          // packed f32x2 accumulators
    for (int k0 = 0; k0 < K; k0 += 16) {
        {
            int r = tid >> 2;
            int c = (tid & 3) * 4;
            float4 v = make_float4(0.f, 0.f, 0.f, 0.f);
            if (bm + r < M)
                v = *reinterpret_cast<const float4*>(&A[(size_t)(bm + r) * K + k0 + c]);
            As[c + 0][r] = v.x; As[c + 1][r] = v.y;
            As[c + 2][r] = v.z; As[c + 3][r] = v.w;
        }
        {
            int r = tid >> 4;
            int c = (tid & 15) * 4;
            float4 v = *reinterpret_cast<const float4*>(&B[(size_t)(k0 + r) * N + bn + c]);
            Bs[r][c + 0] = v.x; Bs[r][c + 1] = v.y;
            Bs[r][c + 2] = v.z; Bs[r][c + 3] = v.w;
        }
        __syncthreads();
        #pragma unroll
        for (int k = 0; k < 16; k++) {
            float4 a = *reinterpret_cast<const float4*>(&As[k][ty * 4]);
            ulonglong2 bp = *reinterpret_cast<const ulonglong2*>(&Bs[k][tx * 4]);
            float av[4] = {a.x, a.y, a.z, a.w};
            #pragma unroll
            for (int i = 0; i < 4; i++) {
                unsigned long long ap;
                asm("mov.b64 %0, {%1, %1};" : "=l"(ap) : "f"(av[i]));
                asm("fma.rn.f32x2 %0, %1, %2, %0;" : "+l"(acc2[i][0]) : "l"(ap), "l"(bp.x));
                asm("fma.rn.f32x2 %0, %1, %2, %0;" : "+l"(acc2[i][1]) : "l"(ap), "l"(bp.y));
            }
        }
        __syncthreads();
    }
    #pragma unroll
    for (int i = 0; i < 4; i++) {
        int m = bm + ty * 4 + i;
        if (m < M) {
            float s = g_rs_out[m];
            float c0, c1, c2, c3;
            asm("mov.b64 {%0, %1}, %2;" : "=f"(c0), "=f"(c1) : "l"(acc2[i][0]));
            asm("mov.b64 {%0, %1}, %2;" : "=f"(c2), "=f"(c3) : "l"(acc2[i][1]));
            float4 o = make_float4(c0 * s, c1 * s, c2 * s, c3 * s);
            *reinterpret_cast<float4*>(&C[(size_t)m * N + bn + tx * 4]) = o;
        }
    }
}

__global__ void k_gemm1(const float* __restrict__ X, const float* __restrict__ W1) {
    gemm_rs_body(X, W1, &g_A1[0], N_NODES, F_H, F_IN);
}
__global__ void k_gemm2(const float* __restrict__ W2) {
    gemm_rs_body(&g_H[0], W2, &g_A2[0], N_NODES, F_OUT, F_H);
}

// ---------------- SpMM (CSR gather, scalar per-feature: R4-proven) ------------
template <int F, bool RELU>
__device__ __forceinline__ void spmm_body(const float* __restrict__ X,
                                          const float* __restrict__ bias,
                                          float* __restrict__ out)
{
    const int row = blockIdx.x;
    const int f   = threadIdx.x;
    const int beg = g_row_ptr[row];
    const int end = g_row_ptr[row + 1];
    __shared__ int sidx[256];
    float a0 = 0.f, a1 = 0.f, a2 = 0.f, a3 = 0.f;
    for (int base = beg; base < end; base += 256) {
        int cnt = min(256, end - base);
        for (int i = f; i < cnt; i += F) sidx[i] = g_src_sorted[base + i];
        __syncthreads();
        int i = 0;
        for (; i + 4 <= cnt; i += 4) {
            a0 += X[(size_t)sidx[i + 0] * F + f];
            a1 += X[(size_t)sidx[i + 1] * F + f];
            a2 += X[(size_t)sidx[i + 2] * F + f];
            a3 += X[(size_t)sidx[i + 3] * F + f];
        }
        for (; i < cnt; i++) a0 += X[(size_t)sidx[i] * F + f];
        __syncthreads();
    }
    float v = (a0 + a1 + a2 + a3) * g_rs_in[row] + bias[f];
    if (RELU) v = fmaxf(v, 0.f);
    out[(size_t)row * F + f] = v;
}

__global__ void k_spmm1(const float* __restrict__ b1) {
    spmm_body<F_H, true>(&g_A1[0], b1, &g_H[0]);
}
__global__ void k_spmm2(const float* __restrict__ b2, float* __restrict__ out) {
    spmm_body<F_OUT, false>(&g_A2[0], b2, out);
}

// ---------------- launch ----------------
extern "C" void kernel_launch(void* const* d_in, const int* in_sizes, int n_in,
                              void* d_out, int out_size) {
    const float* X   = (const float*)d_in[0];
    const int*   src = (const int*)d_in[1];   // int32 or int64 (device-detected)
    const int*   dst = (const int*)d_in[2];
    const float* W1  = (const float*)d_in[3];
    const float* b1  = (const float*)d_in[4];
    const float* W2  = (const float*)d_in[5];
    const float* b2  = (const float*)d_in[6];
    float* out = (float*)d_out;

    const int NB_EDGE = (N_EDGES + 255) / 256;   // 2500

    k_detect    <<<1, 256>>>(src);
    k_degrees   <<<NB_EDGE, 256>>>(src, dst);
    k_scan_rsqrt<<<1, 1024>>>();
    k_fill      <<<NB_EDGE, 256>>>(src, dst);

    dim3 grid1(F_H / 64, (N_NODES + 63) / 64);
    k_gemm1<<<grid1, 256>>>(X, W1);
    k_spmm1<<<N_NODES, F_H>>>(b1);

    dim3 grid2(F_OUT / 64, (N_NODES + 63) / 64);
    k_gemm2<<<grid2, 256>>>(W2);
    k_spmm2<<<N_NODES, F_OUT>>>(b2, out);
}

// round 11
// speedup vs baseline: 1.7010x; 1.0829x over previous
#include <cuda_runtime.h>
#include <cuda_bf16.h>

#define N_NODES 10000
#define N_EDGES 640000
#define F_IN 128
#define F_H 128
#define F_OUT 64

// ---------------- scratch (device globals; zero-initialized at load) -----------
__device__ int   g_is_i32;               // 1 => indices are int32, 0 => int64
__device__ int   g_deg_in [N_NODES];     // re-zeroed by k_scan_rsqrt each call
__device__ int   g_deg_out[N_NODES];     // re-zeroed by k_scan_rsqrt each call
__device__ float g_rs_in  [N_NODES];
__device__ float g_rs_out [N_NODES];
__device__ int   g_row_ptr[N_NODES + 1];
__device__ int   g_rank   [N_EDGES];     // rank of edge within its dst row
__device__ int   g_src_sorted[N_EDGES];
__device__ __align__(16) __nv_bfloat162 g_A1b[N_NODES * F_H / 2];   // (X@W1)*rs_out, bf16
__device__ __align__(16) float          g_H  [N_NODES * F_H];       // layer-1 out (fp32)
__device__ __align__(16) __nv_bfloat162 g_A2b[N_NODES * F_OUT / 2]; // (H@W2)*rs_out, bf16

// ---------------- dtype detect (single block) ----------------------------------
__global__ void k_detect(const int* __restrict__ src) {
    int v = 0;
    #pragma unroll
    for (int r = 0; r < 8; r++) v |= src[2 * (threadIdx.x + 256 * r) + 1];
    #pragma unroll
    for (int o = 16; o; o >>= 1) v |= __shfl_xor_sync(0xFFFFFFFFu, v, o);
    __shared__ int sred[8];
    if ((threadIdx.x & 31) == 0) sred[threadIdx.x >> 5] = v;
    __syncthreads();
    if (threadIdx.x == 0) {
        int a = 0;
        #pragma unroll
        for (int w = 0; w < 8; w++) a |= sred[w];
        g_is_i32 = (a != 0) ? 1 : 0;
    }
}

// ---------------- degrees + rank capture (1 edge/thread) ------------------------
__global__ void k_degrees(const int* __restrict__ src,
                          const int* __restrict__ dst) {
    int e = blockIdx.x * 256 + threadIdx.x;
    if (e < N_EDGES) {
        const int i32 = g_is_i32;
        int s = i32 ? src[e] : src[2 * e];
        int d = i32 ? dst[e] : dst[2 * e];
        atomicAdd(&g_deg_out[s], 1);                 // no return -> REDG
        g_rank[e] = atomicAdd(&g_deg_in[d], 1);      // return = rank in row
    }
}

// ---------------- fused: rsqrt + single-pass exclusive scan + re-zero -----------
__global__ void k_scan_rsqrt() {
    constexpr int PT = 10;   // 1024*10 >= 10000
    const int tid  = threadIdx.x;
    const int lane = tid & 31, warp = tid >> 5;

    for (int i = tid; i < N_NODES; i += 1024) {
        g_rs_in [i] = rsqrtf((float)max(g_deg_in [i], 1));
        g_rs_out[i] = rsqrtf((float)max(g_deg_out[i], 1));
    }

    int base = tid * PT;
    int v[PT];
    int tot = 0;
    #pragma unroll
    for (int j = 0; j < PT; j++) {
        int i = base + j;
        v[j] = (i < N_NODES) ? g_deg_in[i] : 0;
        tot += v[j];
    }

    __shared__ int wsum[32];
    int x = tot;
    #pragma unroll
    for (int o = 1; o < 32; o <<= 1) {
        int t = __shfl_up_sync(0xFFFFFFFFu, x, o);
        if (lane >= o) x += t;
    }
    if (lane == 31) wsum[warp] = x;
    __syncthreads();
    if (warp == 0) {
        int w = wsum[lane];
        #pragma unroll
        for (int o = 1; o < 32; o <<= 1) {
            int t = __shfl_up_sync(0xFFFFFFFFu, w, o);
            if (lane >= o) w += t;
        }
        wsum[lane] = w;
    }
    __syncthreads();
    int excl = (x - tot) + (warp ? wsum[warp - 1] : 0);

    if (tid == 0) g_row_ptr[0] = 0;
    int run = excl;
    #pragma unroll
    for (int j = 0; j < PT; j++) {
        int i = base + j;
        run += v[j];
        if (i < N_NODES) g_row_ptr[i + 1] = run;
    }

    __syncthreads();
    for (int i = tid; i < N_NODES; i += 1024) {
        g_deg_in[i] = 0; g_deg_out[i] = 0;
    }
}

// ---------------- fill: atomic-free slot computation ---------------------------
__global__ void k_fill(const int* __restrict__ src,
                       const int* __restrict__ dst) {
    int e = blockIdx.x * 256 + threadIdx.x;
    if (e < N_EDGES) {
        const int i32 = g_is_i32;
        int s = i32 ? src[e] : src[2 * e];
        int d = i32 ? dst[e] : dst[2 * e];
        g_src_sorted[g_row_ptr[d] + g_rank[e]] = s;
    }
}

// ---------------- GEMM body (256 thr, BM=BN=64, BK=16, 4x4, FFMA2 inner) ------
// Writes C = (A@B)*rs_out as bf16 pairs.
__device__ __forceinline__ void gemm_rs_body_bf16(
    const float* __restrict__ A, const float* __restrict__ B,
    __nv_bfloat162* __restrict__ C2, int M, int N, int K)
{
    __shared__ __align__(16) float As[16][68];
    __shared__ __align__(16) float Bs[16][64];
    int tid = threadIdx.x;
    int tx = tid & 15, ty = tid >> 4;
    int bm = blockIdx.y * 64;
    int bn = blockIdx.x * 64;
    unsigned long long acc2[4][2] = {};
    for (int k0 = 0; k0 < K; k0 += 16) {
        {
            int r = tid >> 2;
            int c = (tid & 3) * 4;
            float4 v = make_float4(0.f, 0.f, 0.f, 0.f);
            if (bm + r < M)
                v = *reinterpret_cast<const float4*>(&A[(size_t)(bm + r) * K + k0 + c]);
            As[c + 0][r] = v.x; As[c + 1][r] = v.y;
            As[c + 2][r] = v.z; As[c + 3][r] = v.w;
        }
        {
            int r = tid >> 4;
            int c = (tid & 15) * 4;
            float4 v = *reinterpret_cast<const float4*>(&B[(size_t)(k0 + r) * N + bn + c]);
            Bs[r][c + 0] = v.x; Bs[r][c + 1] = v.y;
            Bs[r][c + 2] = v.z; Bs[r][c + 3] = v.w;
        }
        __syncthreads();
        #pragma unroll
        for (int k = 0; k < 16; k++) {
            float4 a = *reinterpret_cast<const float4*>(&As[k][ty * 4]);
            ulonglong2 bp = *reinterpret_cast<const ulonglong2*>(&Bs[k][tx * 4]);
            float av[4] = {a.x, a.y, a.z, a.w};
            #pragma unroll
            for (int i = 0; i < 4; i++) {
                unsigned long long ap;
                asm("mov.b64 %0, {%1, %1};" : "=l"(ap) : "f"(av[i]));
                asm("fma.rn.f32x2 %0, %1, %2, %0;" : "+l"(acc2[i][0]) : "l"(ap), "l"(bp.x));
                asm("fma.rn.f32x2 %0, %1, %2, %0;" : "+l"(acc2[i][1]) : "l"(ap), "l"(bp.y));
            }
        }
        __syncthreads();
    }
    const int NC = N / 2;
    #pragma unroll
    for (int i = 0; i < 4; i++) {
        int m = bm + ty * 4 + i;
        if (m < M) {
            float s = g_rs_out[m];
            float c0, c1, c2, c3;
            asm("mov.b64 {%0, %1}, %2;" : "=f"(c0), "=f"(c1) : "l"(acc2[i][0]));
            asm("mov.b64 {%0, %1}, %2;" : "=f"(c2), "=f"(c3) : "l"(acc2[i][1]));
            __nv_bfloat162 p0 = __float22bfloat162_rn(make_float2(c0 * s, c1 * s));
            __nv_bfloat162 p1 = __float22bfloat162_rn(make_float2(c2 * s, c3 * s));
            uint2 pk;
            pk.x = *reinterpret_cast<unsigned int*>(&p0);
            pk.y = *reinterpret_cast<unsigned int*>(&p1);
            // FIX (R10 bug): include the column-tile offset bn/2
            *reinterpret_cast<uint2*>(&C2[(size_t)m * NC + (bn >> 1) + tx * 2]) = pk;
        }
    }
}

__global__ void k_gemm1(const float* __restrict__ X, const float* __restrict__ W1) {
    gemm_rs_body_bf16(X, W1, &g_A1b[0], N_NODES, F_H, F_IN);
}
__global__ void k_gemm2(const float* __restrict__ W2) {
    gemm_rs_body_bf16(&g_H[0], W2, &g_A2b[0], N_NODES, F_OUT, F_H);
}

// ---------------- SpMM (CSR gather over bf16x2 lanes, fp32 accumulate) --------
// F/2 threads per row; thread t owns feature pair (2t, 2t+1).
template <int F, bool RELU>
__device__ __forceinline__ void spmm_bf_body(const __nv_bfloat162* __restrict__ X2,
                                             const float* __restrict__ bias,
                                             float* __restrict__ out)
{
    constexpr int T = F / 2;
    const int row = blockIdx.x;
    const int t   = threadIdx.x;
    const int beg = g_row_ptr[row];
    const int end = g_row_ptr[row + 1];
    __shared__ int sidx[256];
    float2 a0 = {0.f, 0.f}, a1 = {0.f, 0.f}, a2 = {0.f, 0.f}, a3 = {0.f, 0.f};
    for (int base = beg; base < end; base += 256) {
        int cnt = min(256, end - base);
        for (int i = t; i < cnt; i += T) sidx[i] = g_src_sorted[base + i];
        __syncthreads();
        int i = 0;
        for (; i + 4 <= cnt; i += 4) {
            float2 v0 = __bfloat1622float2(X2[(size_t)sidx[i + 0] * T + t]);
            float2 v1 = __bfloat1622float2(X2[(size_t)sidx[i + 1] * T + t]);
            float2 v2 = __bfloat1622float2(X2[(size_t)sidx[i + 2] * T + t]);
            float2 v3 = __bfloat1622float2(X2[(size_t)sidx[i + 3] * T + t]);
            a0.x += v0.x; a0.y += v0.y;
            a1.x += v1.x; a1.y += v1.y;
            a2.x += v2.x; a2.y += v2.y;
            a3.x += v3.x; a3.y += v3.y;
        }
        for (; i < cnt; i++) {
            float2 v = __bfloat1622float2(X2[(size_t)sidx[i] * T + t]);
            a0.x += v.x; a0.y += v.y;
        }
        __syncthreads();
    }
    float r = g_rs_in[row];
    float2 b = reinterpret_cast<const float2*>(bias)[t];
    float2 o;
    o.x = (a0.x + a1.x + a2.x + a3.x) * r + b.x;
    o.y = (a0.y + a1.y + a2.y + a3.y) * r + b.y;
    if (RELU) { o.x = fmaxf(o.x, 0.f); o.y = fmaxf(o.y, 0.f); }
    reinterpret_cast<float2*>(out)[(size_t)row * T + t] = o;
}

__global__ void k_spmm1(const float* __restrict__ b1) {
    spmm_bf_body<F_H, true>(&g_A1b[0], b1, &g_H[0]);
}
__global__ void k_spmm2(const float* __restrict__ b2, float* __restrict__ out) {
    spmm_bf_body<F_OUT, false>(&g_A2b[0], b2, out);
}

// ---------------- launch ----------------
extern "C" void kernel_launch(void* const* d_in, const int* in_sizes, int n_in,
                              void* d_out, int out_size) {
    const float* X   = (const float*)d_in[0];
    const int*   src = (const int*)d_in[1];   // int32 or int64 (device-detected)
    const int*   dst = (const int*)d_in[2];
    const float* W1  = (const float*)d_in[3];
    const float* b1  = (const float*)d_in[4];
    const float* W2  = (const float*)d_in[5];
    const float* b2  = (const float*)d_in[6];
    float* out = (float*)d_out;

    const int NB_EDGE = (N_EDGES + 255) / 256;   // 2500

    k_detect    <<<1, 256>>>(src);
    k_degrees   <<<NB_EDGE, 256>>>(src, dst);
    k_scan_rsqrt<<<1, 1024>>>();
    k_fill      <<<NB_EDGE, 256>>>(src, dst);

    dim3 grid1(F_H / 64, (N_NODES + 63) / 64);
    k_gemm1<<<grid1, 256>>>(X, W1);
    k_spmm1<<<N_NODES, F_H / 2>>>(b1);

    dim3 grid2(F_OUT / 64, (N_NODES + 63) / 64);
    k_gemm2<<<grid2, 256>>>(W2);
    k_spmm2<<<N_NODES, F_OUT / 2>>>(b2, out);
}

// round 12
// speedup vs baseline: 1.7698x; 1.0404x over previous
#include <cuda_runtime.h>
#include <cuda_bf16.h>

#define N_NODES 10000
#define N_EDGES 640000
#define F_IN 128
#define F_H 128
#define F_OUT 64

// ---------------- scratch (device globals; zero-initialized at load) -----------
__device__ int   g_is_i32;               // 1 => indices are int32, 0 => int64
__device__ int   g_deg_in [N_NODES];     // re-zeroed by k_scan_rsqrt each call
__device__ int   g_deg_out[N_NODES];     // re-zeroed by k_scan_rsqrt each call
__device__ float g_rs_in  [N_NODES];
__device__ float g_rs_out [N_NODES];
__device__ int   g_row_ptr[N_NODES + 1];
__device__ long long g_pack[N_EDGES];    // s | d<<14 | rank<<28
__device__ int   g_src_sorted[N_EDGES];
__device__ __align__(16) __nv_bfloat162 g_A1b[N_NODES * F_H / 2];   // (X@W1)*rs_out, bf16
__device__ __align__(16) float          g_H  [N_NODES * F_H];       // layer-1 out (fp32)
__device__ __align__(16) __nv_bfloat162 g_A2b[N_NODES * F_OUT / 2]; // (H@W2)*rs_out, bf16

// ---------------- dtype detect (single block) ----------------------------------
__global__ void k_detect(const int* __restrict__ src) {
    int v = 0;
    #pragma unroll
    for (int r = 0; r < 8; r++) v |= src[2 * (threadIdx.x + 256 * r) + 1];
    #pragma unroll
    for (int o = 16; o; o >>= 1) v |= __shfl_xor_sync(0xFFFFFFFFu, v, o);
    __shared__ int sred[8];
    if ((threadIdx.x & 31) == 0) sred[threadIdx.x >> 5] = v;
    __syncthreads();
    if (threadIdx.x == 0) {
        int a = 0;
        #pragma unroll
        for (int w = 0; w < 8; w++) a |= sred[w];
        g_is_i32 = (a != 0) ? 1 : 0;
    }
}

// ---------------- degrees + rank capture + packed edge record -------------------
__global__ void k_degrees(const int* __restrict__ src,
                          const int* __restrict__ dst) {
    int e = blockIdx.x * 256 + threadIdx.x;
    if (e < N_EDGES) {
        const int i32 = g_is_i32;
        int s = i32 ? src[e] : src[2 * e];
        int d = i32 ? dst[e] : dst[2 * e];
        atomicAdd(&g_deg_out[s], 1);                 // no return -> REDG
        int rank = atomicAdd(&g_deg_in[d], 1);       // return = rank in row
        g_pack[e] = (long long)s | ((long long)d << 14) | ((long long)rank << 28);
    }
}

// ---------------- fused: rsqrt + single-pass exclusive scan + re-zero -----------
__global__ void k_scan_rsqrt() {
    constexpr int PT = 10;   // 1024*10 >= 10000
    const int tid  = threadIdx.x;
    const int lane = tid & 31, warp = tid >> 5;

    for (int i = tid; i < N_NODES; i += 1024) {
        g_rs_in [i] = rsqrtf((float)max(g_deg_in [i], 1));
        g_rs_out[i] = rsqrtf((float)max(g_deg_out[i], 1));
    }

    int base = tid * PT;
    int v[PT];
    int tot = 0;
    #pragma unroll
    for (int j = 0; j < PT; j++) {
        int i = base + j;
        v[j] = (i < N_NODES) ? g_deg_in[i] : 0;
        tot += v[j];
    }

    __shared__ int wsum[32];
    int x = tot;
    #pragma unroll
    for (int o = 1; o < 32; o <<= 1) {
        int t = __shfl_up_sync(0xFFFFFFFFu, x, o);
        if (lane >= o) x += t;
    }
    if (lane == 31) wsum[warp] = x;
    __syncthreads();
    if (warp == 0) {
        int w = wsum[lane];
        #pragma unroll
        for (int o = 1; o < 32; o <<= 1) {
            int t = __shfl_up_sync(0xFFFFFFFFu, w, o);
            if (lane >= o) w += t;
        }
        wsum[lane] = w;
    }
    __syncthreads();
    int excl = (x - tot) + (warp ? wsum[warp - 1] : 0);

    if (tid == 0) g_row_ptr[0] = 0;
    int run = excl;
    #pragma unroll
    for (int j = 0; j < PT; j++) {
        int i = base + j;
        run += v[j];
        if (i < N_NODES) g_row_ptr[i + 1] = run;
    }

    __syncthreads();
    for (int i = tid; i < N_NODES; i += 1024) {
        g_deg_in[i] = 0; g_deg_out[i] = 0;
    }
}

// ---------------- fill: one packed load, atomic-free scatter --------------------
__global__ void k_fill() {
    int e = blockIdx.x * 256 + threadIdx.x;
    if (e < N_EDGES) {
        long long w = g_pack[e];
        int s    = (int)(w & 0x3FFF);
        int d    = (int)((w >> 14) & 0x3FFF);
        int rank = (int)(w >> 28);
        g_src_sorted[g_row_ptr[d] + rank] = s;
    }
}

// ---------------- GEMM body (256 thr, BM=BN=64, BK=16, 4x4, FFMA2 inner) ------
// Writes C = (A@B)*rs_out as bf16 pairs.
__device__ __forceinline__ void gemm_rs_body_bf16(
    const float* __restrict__ A, const float* __restrict__ B,
    __nv_bfloat162* __restrict__ C2, int M, int N, int K)
{
    __shared__ __align__(16) float As[16][68];
    __shared__ __align__(16) float Bs[16][64];
    int tid = threadIdx.x;
    int tx = tid & 15, ty = tid >> 4;
    int bm = blockIdx.y * 64;
    int bn = blockIdx.x * 64;
    unsigned long long acc2[4][2] = {};
    for (int k0 = 0; k0 < K; k0 += 16) {
        {
            int r = tid >> 2;
            int c = (tid & 3) * 4;
            float4 v = make_float4(0.f, 0.f, 0.f, 0.f);
            if (bm + r < M)
                v = *reinterpret_cast<const float4*>(&A[(size_t)(bm + r) * K + k0 + c]);
            As[c + 0][r] = v.x; As[c + 1][r] = v.y;
            As[c + 2][r] = v.z; As[c + 3][r] = v.w;
        }
        {
            int r = tid >> 4;
            int c = (tid & 15) * 4;
            float4 v = *reinterpret_cast<const float4*>(&B[(size_t)(k0 + r) * N + bn + c]);
            Bs[r][c + 0] = v.x; Bs[r][c + 1] = v.y;
            Bs[r][c + 2] = v.z; Bs[r][c + 3] = v.w;
        }
        __syncthreads();
        #pragma unroll
        for (int k = 0; k < 16; k++) {
            float4 a = *reinterpret_cast<const float4*>(&As[k][ty * 4]);
            ulonglong2 bp = *reinterpret_cast<const ulonglong2*>(&Bs[k][tx * 4]);
            float av[4] = {a.x, a.y, a.z, a.w};
            #pragma unroll
            for (int i = 0; i < 4; i++) {
                unsigned long long ap;
                asm("mov.b64 %0, {%1, %1};" : "=l"(ap) : "f"(av[i]));
                asm("fma.rn.f32x2 %0, %1, %2, %0;" : "+l"(acc2[i][0]) : "l"(ap), "l"(bp.x));
                asm("fma.rn.f32x2 %0, %1, %2, %0;" : "+l"(acc2[i][1]) : "l"(ap), "l"(bp.y));
            }
        }
        __syncthreads();
    }
    const int NC = N / 2;
    #pragma unroll
    for (int i = 0; i < 4; i++) {
        int m = bm + ty * 4 + i;
        if (m < M) {
            float s = g_rs_out[m];
            float c0, c1, c2, c3;
            asm("mov.b64 {%0, %1}, %2;" : "=f"(c0), "=f"(c1) : "l"(acc2[i][0]));
            asm("mov.b64 {%0, %1}, %2;" : "=f"(c2), "=f"(c3) : "l"(acc2[i][1]));
            __nv_bfloat162 p0 = __float22bfloat162_rn(make_float2(c0 * s, c1 * s));
            __nv_bfloat162 p1 = __float22bfloat162_rn(make_float2(c2 * s, c3 * s));
            uint2 pk;
            pk.x = *reinterpret_cast<unsigned int*>(&p0);
            pk.y = *reinterpret_cast<unsigned int*>(&p1);
            *reinterpret_cast<uint2*>(&C2[(size_t)m * NC + (bn >> 1) + tx * 2]) = pk;
        }
    }
}

__global__ void k_gemm1(const float* __restrict__ X, const float* __restrict__ W1) {
    gemm_rs_body_bf16(X, W1, &g_A1b[0], N_NODES, F_H, F_IN);
}
__global__ void k_gemm2(const float* __restrict__ W2) {
    gemm_rs_body_bf16(&g_H[0], W2, &g_A2b[0], N_NODES, F_OUT, F_H);
}

// ---------------- SpMM (CSR gather over bf16x2 lanes, fp32 accumulate) --------
template <int F, bool RELU>
__device__ __forceinline__ void spmm_bf_body(const __nv_bfloat162* __restrict__ X2,
                                             const float* __restrict__ bias,
                                             float* __restrict__ out)
{
    constexpr int T = F / 2;
    const int row = blockIdx.x;
    const int t   = threadIdx.x;
    const int beg = g_row_ptr[row];
    const int end = g_row_ptr[row + 1];
    __shared__ int sidx[256];
    float2 a0 = {0.f, 0.f}, a1 = {0.f, 0.f}, a2 = {0.f, 0.f}, a3 = {0.f, 0.f};
    for (int base = beg; base < end; base += 256) {
        int cnt = min(256, end - base);
        for (int i = t; i < cnt; i += T) sidx[i] = g_src_sorted[base + i];
        __syncthreads();
        int i = 0;
        for (; i + 4 <= cnt; i += 4) {
            float2 v0 = __bfloat1622float2(X2[(size_t)sidx[i + 0] * T + t]);
            float2 v1 = __bfloat1622float2(X2[(size_t)sidx[i + 1] * T + t]);
            float2 v2 = __bfloat1622float2(X2[(size_t)sidx[i + 2] * T + t]);
            float2 v3 = __bfloat1622float2(X2[(size_t)sidx[i + 3] * T + t]);
            a0.x += v0.x; a0.y += v0.y;
            a1.x += v1.x; a1.y += v1.y;
            a2.x += v2.x; a2.y += v2.y;
            a3.x += v3.x; a3.y += v3.y;
        }
        for (; i < cnt; i++) {
            float2 v = __bfloat1622float2(X2[(size_t)sidx[i] * T + t]);
            a0.x += v.x; a0.y += v.y;
        }
        __syncthreads();
    }
    float r = g_rs_in[row];
    float2 b = reinterpret_cast<const float2*>(bias)[t];
    float2 o;
    o.x = (a0.x + a1.x + a2.x + a3.x) * r + b.x;
    o.y = (a0.y + a1.y + a2.y + a3.y) * r + b.y;
    if (RELU) { o.x = fmaxf(o.x, 0.f); o.y = fmaxf(o.y, 0.f); }
    reinterpret_cast<float2*>(out)[(size_t)row * T + t] = o;
}

__global__ void k_spmm1(const float* __restrict__ b1) {
    spmm_bf_body<F_H, true>(&g_A1b[0], b1, &g_H[0]);
}
__global__ void k_spmm2(const float* __restrict__ b2, float* __restrict__ out) {
    spmm_bf_body<F_OUT, false>(&g_A2b[0], b2, out);
}

// ---------------- launch ----------------
extern "C" void kernel_launch(void* const* d_in, const int* in_sizes, int n_in,
                              void* d_out, int out_size) {
    const float* X   = (const float*)d_in[0];
    const int*   src = (const int*)d_in[1];   // int32 or int64 (device-detected)
    const int*   dst = (const int*)d_in[2];
    const float* W1  = (const float*)d_in[3];
    const float* b1  = (const float*)d_in[4];
    const float* W2  = (const float*)d_in[5];
    const float* b2  = (const float*)d_in[6];
    float* out = (float*)d_out;

    // side stream + events, created once on the (non-captured) correctness call
    static cudaStream_t s2 = nullptr;
    static cudaEvent_t  ev_fork = nullptr, ev_join = nullptr;
    if (s2 == nullptr) {
        cudaStreamCreateWithFlags(&s2, cudaStreamNonBlocking);
        cudaEventCreateWithFlags(&ev_fork, cudaEventDisableTiming);
        cudaEventCreateWithFlags(&ev_join, cudaEventDisableTiming);
    }

    const int NB_EDGE = (N_EDGES + 255) / 256;   // 2500

    k_detect    <<<1, 256>>>(src);
    k_degrees   <<<NB_EDGE, 256>>>(src, dst);
    k_scan_rsqrt<<<1, 1024>>>();

    // fork AFTER scan: gemm1 (s2) runs concurrently with fill (main) only
    cudaEventRecord(ev_fork, 0);
    cudaStreamWaitEvent(s2, ev_fork, 0);
    dim3 grid1(F_H / 64, (N_NODES + 63) / 64);
    k_gemm1<<<grid1, 256, 0, s2>>>(X, W1);
    cudaEventRecord(ev_join, s2);

    k_fill<<<NB_EDGE, 256>>>();

    cudaStreamWaitEvent(0, ev_join, 0);
    k_spmm1<<<N_NODES, F_H / 2>>>(b1);

    dim3 grid2(F_OUT / 64, (N_NODES + 63) / 64);
    k_gemm2<<<grid2, 256>>>(W2);
    k_spmm2<<<N_NODES, F_OUT / 2>>>(b2, out);
}